// round 6
// baseline (speedup 1.0000x reference)
#include <cuda_runtime.h>
#include <math.h>

#define VOL   2097152              // 128^3
#define NB    4
#define S2D   16384                // 128*128 (z stride)

// Normalized 1-D Gaussian weights (sigma=1.6, 7 taps), sum = 1.
#define W0 0.25603832f   // center
#define W1 0.21061137f   // +-1
#define W2 0.11722290f   // +-2
#define W3 0.04414655f   // +-3

// Scratch (allocation-free contract: __device__ globals)
__device__ float g_a [(size_t)NB * VOL];   // d   smoothed in x,y
__device__ float g_b [(size_t)NB * VOL];   // |curl v| smoothed in x,y

#define F4Z make_float4(0.f, 0.f, 0.f, 0.f)

// x-convolution of a warp-distributed row (lane holds 4 consecutive x) via
// shuffles; zero padding outside [0,127] handled by lane-edge masks.
__device__ __forceinline__ float4 xconv_row(float p0, float p1, float p2, float p3,
                                            int lane) {
    float m1 = __shfl_up_sync(0xffffffffu, p3, 1);
    float m2 = __shfl_up_sync(0xffffffffu, p2, 1);
    float m3 = __shfl_up_sync(0xffffffffu, p1, 1);
    if (lane == 0) { m1 = 0.f; m2 = 0.f; m3 = 0.f; }
    float q1 = __shfl_down_sync(0xffffffffu, p0, 1);
    float q2 = __shfl_down_sync(0xffffffffu, p1, 1);
    float q3 = __shfl_down_sync(0xffffffffu, p2, 1);
    if (lane == 31) { q1 = 0.f; q2 = 0.f; q3 = 0.f; }

    float4 c;
    c.x = W0 * p0 + W1 * (m1 + p1) + W2 * (m2 + p2) + W3 * (m3 + p3);
    c.y = W0 * p1 + W1 * (p0 + p2) + W2 * (m1 + p3) + W3 * (m2 + q1);
    c.z = W0 * p2 + W1 * (p1 + p3) + W2 * (p0 + q1) + W3 * (m1 + q2);
    c.w = W0 * p3 + W1 * (p2 + q1) + W2 * (p1 + q2) + W3 * (p0 + q3);
    return c;
}

// ---------------------------------------------------------------------------
// Fused kernel, register-resident separable smoothing (NO shared memory).
// Block = 8 warps, one (n,z) slice per block.
//   warps 0-3 : |curl v| -> smooth X (shuffles) -> smooth Y (rolling window)
//               over a 32-row strip -> g_b
//   warps 4-7 : d -> same pipeline -> g_a
// fdiff(f,i) = f[min(i,126)+1]-f[min(i,126)]; conv zero-pads the 128 extent.
// u,w rows are streamed (prev/cur/next) so each step needs only 5 float4 LDG.
// ---------------------------------------------------------------------------
__global__ __launch_bounds__(256)
void fused_smooth_kernel(const float* __restrict__ d,
                         const float* __restrict__ v) {
    int tid  = threadIdx.x;
    int lane = tid & 31;
    int wid  = tid >> 5;
    int nz = blockIdx.x;             // n*128 + z
    int n = nz >> 7, z = nz & 127;
    const int xo = lane * 4;

    float4 win[7];
#pragma unroll
    for (int k = 0; k < 7; k++) win[k] = F4Z;

    if (wid < 4) {
        // ================= phase B : |curl v| =================
        const float* pu = v + (size_t)(n * 3 + 0) * VOL + z * S2D;
        const float* pv = v + (size_t)(n * 3 + 1) * VOL + z * S2D;
        const float* pw = v + (size_t)(n * 3 + 2) * VOL + z * S2D;
        const int   dz = (z < 127) ? S2D : -S2D;
        const float ez = (z < 127) ? 1.f : -1.f;
        float* outp = g_b + (size_t)n * VOL + z * S2D;

        const int y0 = wid * 32;
        const int ys = y0 - 3;

        float4 up = F4Z, uc = F4Z, un = F4Z;
        float4 wp = F4Z, wc = F4Z, wn = F4Z;
        if ((unsigned)ys < 128u) {
            un = *(const float4*)(pu + ys * 128 + xo);
            wn = *(const float4*)(pw + ys * 128 + xo);
        }

        for (int y = ys; y <= y0 + 34; ++y) {
            up = uc; uc = un;
            wp = wc; wc = wn;
            int yn = y + 1;
            if ((unsigned)yn < 128u) {
                un = *(const float4*)(pu + yn * 128 + xo);
                wn = *(const float4*)(pw + yn * 128 + xo);
            } else { un = F4Z; wn = F4Z; }

            float4 c = F4Z;
            if ((unsigned)y < 128u) {
                float4 vc = *(const float4*)(pv + y * 128 + xo);
                float4 vz = *(const float4*)(pv + y * 128 + xo + dz);
                float4 uz = *(const float4*)(pu + y * 128 + xo + dz);

                // z-derivatives
                float duz0 = ez * (uz.x - uc.x), duz1 = ez * (uz.y - uc.y);
                float duz2 = ez * (uz.z - uc.z), duz3 = ez * (uz.w - uc.w);
                float dvz0 = ez * (vz.x - vc.x), dvz1 = ez * (vz.y - vc.y);
                float dvz2 = ez * (vz.z - vc.z), dvz3 = ez * (vz.w - vc.w);

                // y-derivatives (clamped fdiff: at y==127 use row126->127 diff)
                float duy0, duy1, duy2, duy3, dwy0, dwy1, dwy2, dwy3;
                if (y < 127) {
                    duy0 = un.x - uc.x; duy1 = un.y - uc.y;
                    duy2 = un.z - uc.z; duy3 = un.w - uc.w;
                    dwy0 = wn.x - wc.x; dwy1 = wn.y - wc.y;
                    dwy2 = wn.z - wc.z; dwy3 = wn.w - wc.w;
                } else {
                    duy0 = uc.x - up.x; duy1 = uc.y - up.y;
                    duy2 = uc.z - up.z; duy3 = uc.w - up.w;
                    dwy0 = wc.x - wp.x; dwy1 = wc.y - wp.y;
                    dwy2 = wc.z - wp.z; dwy3 = wc.w - wp.w;
                }

                // x-derivatives (neighbor from next lane; clamp at x==127)
                float vnx = __shfl_down_sync(0xffffffffu, vc.x, 1);
                float wnx = __shfl_down_sync(0xffffffffu, wc.x, 1);
                float dvx0 = vc.y - vc.x, dvx1 = vc.z - vc.y, dvx2 = vc.w - vc.z;
                float dvx3 = (lane < 31) ? (vnx - vc.w) : (vc.w - vc.z);
                float dwx0 = wc.y - wc.x, dwx1 = wc.z - wc.y, dwx2 = wc.w - wc.z;
                float dwx3 = (lane < 31) ? (wnx - wc.w) : (wc.w - wc.z);

                // curl & norm
                float cu0 = dwy0 - dvz0, cv0 = duz0 - dwx0, cw0 = dvx0 - duy0;
                float cu1 = dwy1 - dvz1, cv1 = duz1 - dwx1, cw1 = dvx1 - duy1;
                float cu2 = dwy2 - dvz2, cv2 = duz2 - dwx2, cw2 = dvx2 - duy2;
                float cu3 = dwy3 - dvz3, cv3 = duz3 - dwx3, cw3 = dvx3 - duy3;
                float p0 = sqrtf(cu0 * cu0 + cv0 * cv0 + cw0 * cw0);
                float p1 = sqrtf(cu1 * cu1 + cv1 * cv1 + cw1 * cw1);
                float p2 = sqrtf(cu2 * cu2 + cv2 * cv2 + cw2 * cw2);
                float p3 = sqrtf(cu3 * cu3 + cv3 * cv3 + cw3 * cw3);

                c = xconv_row(p0, p1, p2, p3, lane);
            }

#pragma unroll
            for (int k = 0; k < 6; k++) win[k] = win[k + 1];
            win[6] = c;

            if (y >= y0 + 3) {
                int yo = y - 3;
                float4 r;
                r.x = W0 * win[3].x + W1 * (win[2].x + win[4].x)
                    + W2 * (win[1].x + win[5].x) + W3 * (win[0].x + win[6].x);
                r.y = W0 * win[3].y + W1 * (win[2].y + win[4].y)
                    + W2 * (win[1].y + win[5].y) + W3 * (win[0].y + win[6].y);
                r.z = W0 * win[3].z + W1 * (win[2].z + win[4].z)
                    + W2 * (win[1].z + win[5].z) + W3 * (win[0].z + win[6].z);
                r.w = W0 * win[3].w + W1 * (win[2].w + win[4].w)
                    + W2 * (win[1].w + win[5].w) + W3 * (win[0].w + win[6].w);
                *(float4*)(outp + yo * 128 + xo) = r;
            }
        }
    } else {
        // ================= phase A : smooth(d) =================
        const float* pd = d + (size_t)n * VOL + z * S2D;
        float* outp = g_a + (size_t)n * VOL + z * S2D;

        const int y0 = (wid - 4) * 32;
        const int ys = y0 - 3;

        for (int y = ys; y <= y0 + 34; ++y) {
            float4 c = F4Z;
            if ((unsigned)y < 128u) {
                float4 dc = *(const float4*)(pd + y * 128 + xo);
                c = xconv_row(dc.x, dc.y, dc.z, dc.w, lane);
            }

#pragma unroll
            for (int k = 0; k < 6; k++) win[k] = win[k + 1];
            win[6] = c;

            if (y >= y0 + 3) {
                int yo = y - 3;
                float4 r;
                r.x = W0 * win[3].x + W1 * (win[2].x + win[4].x)
                    + W2 * (win[1].x + win[5].x) + W3 * (win[0].x + win[6].x);
                r.y = W0 * win[3].y + W1 * (win[2].y + win[4].y)
                    + W2 * (win[1].y + win[5].y) + W3 * (win[0].y + win[6].y);
                r.z = W0 * win[3].z + W1 * (win[2].z + win[4].z)
                    + W2 * (win[1].z + win[5].z) + W3 * (win[0].z + win[6].z);
                r.w = W0 * win[3].w + W1 * (win[2].w + win[4].w)
                    + W2 * (win[1].w + win[5].w) + W3 * (win[0].w + win[6].w);
                *(float4*)(outp + yo * 128 + xo) = r;
            }
        }
    }
}

// ---------------------------------------------------------------------------
// Integrate kernel: fused Z-smooth + flip + cumsum + transform + trapezoid
// + clip, with shared-memory staging (unchanged from R5; 25.8us).
// Block = 32 columns x 8 chunks (16 zf-steps each) = 256 threads.
// ---------------------------------------------------------------------------
__global__ __launch_bounds__(256)
void integrate_kernel(float* __restrict__ out) {
    __shared__ float sA[128][32];
    __shared__ float sB[128][32];
    __shared__ float s_sum[8][32];
    __shared__ float s_iv [8][32];

    int tid   = threadIdx.x;
    int cl    = tid & 31;                    // column within block
    int chunk = tid >> 5;                    // 0..7 (one warp per chunk)

    int colg0 = blockIdx.x * 32;
    int n   = colg0 >> 14;
    int yx0 = colg0 & 16383;                 // 16384 % 32 == 0: no n straddle

    const float* Abase = g_a + (size_t)n * VOL + yx0;
    const float* Bbase = g_b + (size_t)n * VOL + yx0;

    // ---------------- Phase 0: stage columns ------------------------------
    for (int i = tid; i < 128 * 8; i += 256) {      // 8 float4 per z-row
        int z = i >> 3, c4 = (i & 7) << 2;
        *(float4*)&sA[z][c4] = *(const float4*)(Abase + z * S2D + c4);
        *(float4*)&sB[z][c4] = *(const float4*)(Bbase + z * S2D + c4);
    }
    __syncthreads();

    const int z0 = 127 - 16 * chunk;         // first z of this chunk (walk down)

    // ---------------- Phase 1: chunk-local sum of smoothed ds -------------
    float a[7];
#pragma unroll
    for (int k = 0; k < 7; k++) {
        int zi = z0 + k - 3;
        a[k] = ((unsigned)zi < 128u) ? sA[zi][cl] : 0.f;
    }
    float S = 0.f;
    {
        int z = z0;
#pragma unroll
        for (int i = 0; i < 16; i++) {
            int pz = z - 4;
            float na = (pz >= 0) ? sA[pz][cl] : 0.f;
            S += W0 * a[3] + W1 * (a[2] + a[4])
               + W2 * (a[1] + a[5]) + W3 * (a[0] + a[6]);
#pragma unroll
            for (int k = 6; k >= 1; k--) a[k] = a[k - 1];
            a[0] = na;
            z--;
        }
    }
    s_sum[chunk][cl] = S;
    __syncthreads();

    float Xoff = 0.f;
#pragma unroll
    for (int c = 0; c < 7; c++)
        if (c < chunk) Xoff += s_sum[c][cl];

    // ---------------- Boundary state for chunk > 0 ------------------------
    float tprev = 0.f, vprev = 0.f;
    if (chunk > 0) {
        int zb = z0 + 1;   // z at zf = 16*chunk - 1; taps all in [0,127]
        vprev = W0 * sB[zb][cl]
              + W1 * (sB[zb - 1][cl] + sB[zb + 1][cl])
              + W2 * (sB[zb - 2][cl] + sB[zb + 2][cl])
              + W3 * (sB[zb - 3][cl] + sB[zb + 3][cl]);
        tprev = (Xoff * 20.f + 1.f) * __expf(-20.f * Xoff);
    }

    // ---------------- Phase 2: full evaluation ----------------------------
    float b[7];
#pragma unroll
    for (int k = 0; k < 7; k++) {
        int zi = z0 + k - 3;
        if ((unsigned)zi < 128u) {
            a[k] = sA[zi][cl];
            b[k] = sB[zi][cl];
        } else {
            a[k] = 0.f; b[k] = 0.f;
        }
    }

    float xacc = Xoff, iv = 0.f;
    int z = z0;
#pragma unroll
    for (int i = 0; i < 16; i++) {
        int pz = z - 4;
        float na = 0.f, nb = 0.f;
        if (pz >= 0) { na = sA[pz][cl]; nb = sB[pz][cl]; }

        float ds_s = W0 * a[3] + W1 * (a[2] + a[4])
                   + W2 * (a[1] + a[5]) + W3 * (a[0] + a[6]);
        float vn_s = W0 * b[3] + W1 * (b[2] + b[4])
                   + W2 * (b[1] + b[5]) + W3 * (b[0] + b[6]);

        xacc += ds_s;
        float tt = (xacc * 20.f + 1.f) * __expf(-20.f * xacc);

        if (i == 0 && chunk == 0)
            iv = (1.f - tt) * vn_s;                       // front term
        else
            iv += (tprev - tt) * (vprev + vn_s) * 0.5f;   // trapezoid
        tprev = tt; vprev = vn_s;

#pragma unroll
        for (int k = 6; k >= 1; k--) { a[k] = a[k - 1]; b[k] = b[k - 1]; }
        a[0] = na; b[0] = nb;
        z--;
    }

    s_iv[chunk][cl] = iv;
    __syncthreads();

    if (chunk == 0) {
        float tot = iv;
#pragma unroll
        for (int c = 1; c < 8; c++) tot += s_iv[c][cl];
        out[colg0 + cl] = fminf(fmaxf(tot, 0.f), 1.f);
    }
}

// ---------------------------------------------------------------------------
extern "C" void kernel_launch(void* const* d_in, const int* in_sizes, int n_in,
                              void* d_out, int out_size) {
    const float* d = (const float*)d_in[0];
    const float* v = (const float*)d_in[1];
    if (in_sizes[0] > in_sizes[1]) {   // safety: d is the smaller tensor
        const float* tmp = d; d = v; v = tmp;
    }
    float* out = (float*)d_out;

    fused_smooth_kernel<<<NB * 128, 256>>>(d, v);   // g_a (d) and g_b (|curl v|)

    integrate_kernel<<<65536 / 32, 256>>>(out);
}

// round 7
// speedup vs baseline: 1.4964x; 1.4964x over previous
#include <cuda_runtime.h>
#include <math.h>

#define VOL   2097152              // 128^3
#define NB    4
#define S2D   16384                // 128*128 (z stride)

// Normalized 1-D Gaussian weights (sigma=1.6, 7 taps), sum = 1.
#define W0 0.25603832f   // center
#define W1 0.21061137f   // +-1
#define W2 0.11722290f   // +-2
#define W3 0.04414655f   // +-3

// Scratch (allocation-free contract: __device__ globals)
__device__ float g_a [(size_t)NB * VOL];   // d   smoothed in x,y
__device__ float g_b [(size_t)NB * VOL];   // |curl v| smoothed in x,y

#define TSX 64
#define TSY 32
#define LDY 38   // TSY + 6 (y halo rows)
#define NQ  18   // quads per halo row: covers gx in [tx0-4, tx0+68)
#define SPX 72   // NQ*4 floats per smem row (288B, 16B-multiple)

#define F4Z make_float4(0.f, 0.f, 0.f, 0.f)

// ---------------------------------------------------------------------------
// Fused kernel (R5 tile structure, fully 128-bit vectorized):
//   phase A: d  -> separable X,Y smooth -> g_a
//   phase B: |curl v| -> separable X,Y smooth -> g_b
// Halo x-range [tx0-4, tx0+68) = 18 four-aligned quads, each fully in range
// or fully out (tx0 multiple of 64), so every access is float4.
// s_in[ly][lx] holds gx = tx0 - 4 + lx. Output ox reads lx = ox+1 .. ox+7.
// fdiff clamp via diff = e*(f[o+delta]-f[o]) with (delta,e) flipped at i==127.
// Convolution zero-pads outside the 128x128 slice.
// ---------------------------------------------------------------------------
__global__ __launch_bounds__(256)
void fused_smooth_kernel(const float* __restrict__ d,
                         const float* __restrict__ v) {
    int nz = blockIdx.z;             // n*128 + z
    int n = nz >> 7, z = nz & 127;
    int tx0 = blockIdx.x * TSX;
    int ty0 = blockIdx.y * TSY;

    __shared__ __align__(16) float s_in [LDY][SPX];
    __shared__ __align__(16) float s_tmp[LDY][TSX];

    int tid = threadIdx.x;

    // ======================= phase A : smooth(d) =========================
    {
        const float* slice = d + (size_t)n * VOL + z * S2D;
        for (int i = tid; i < LDY * NQ; i += 256) {
            int ly = i / NQ, q = i - ly * NQ;
            int gy = ty0 + ly - 3, gx = tx0 + q * 4 - 4;
            float4 val = F4Z;
            if ((unsigned)gy < 128u && (unsigned)gx < 128u)   // gx 4-aligned
                val = *(const float4*)(slice + gy * 128 + gx);
            *(float4*)&s_in[ly][q * 4] = val;
        }
    }
    __syncthreads();

    // x-pass: 3 aligned LDS.128 per 4 outputs
    for (int i = tid; i < LDY * 16; i += 256) {
        int ly = i >> 4, ox = (i & 15) * 4;
        float4 a = *(const float4*)&s_in[ly][ox];
        float4 b = *(const float4*)&s_in[ly][ox + 4];
        float4 c = *(const float4*)&s_in[ly][ox + 8];
        float4 r;
        r.x = W0 * b.x + W1 * (a.w + b.y) + W2 * (a.z + b.z) + W3 * (a.y + b.w);
        r.y = W0 * b.y + W1 * (b.x + b.z) + W2 * (a.w + b.w) + W3 * (a.z + c.x);
        r.z = W0 * b.z + W1 * (b.y + b.w) + W2 * (b.x + c.x) + W3 * (a.w + c.y);
        r.w = W0 * b.w + W1 * (b.z + c.x) + W2 * (b.y + c.y) + W3 * (b.x + c.z);
        *(float4*)&s_tmp[ly][ox] = r;
    }
    __syncthreads();

    // y-pass + store, then refill s_in with curl (s_in free after sync above)
    {
        float* outp = g_a + (size_t)n * VOL + z * S2D;
        for (int i = tid; i < TSY * 16; i += 256) {
            int oy = i >> 4, ox = (i & 15) * 4;
            float4 t0 = *(const float4*)&s_tmp[oy    ][ox];
            float4 t1 = *(const float4*)&s_tmp[oy + 1][ox];
            float4 t2 = *(const float4*)&s_tmp[oy + 2][ox];
            float4 t3 = *(const float4*)&s_tmp[oy + 3][ox];
            float4 t4 = *(const float4*)&s_tmp[oy + 4][ox];
            float4 t5 = *(const float4*)&s_tmp[oy + 5][ox];
            float4 t6 = *(const float4*)&s_tmp[oy + 6][ox];
            float4 r;
            r.x = W0 * t3.x + W1 * (t2.x + t4.x) + W2 * (t1.x + t5.x) + W3 * (t0.x + t6.x);
            r.y = W0 * t3.y + W1 * (t2.y + t4.y) + W2 * (t1.y + t5.y) + W3 * (t0.y + t6.y);
            r.z = W0 * t3.z + W1 * (t2.z + t4.z) + W2 * (t1.z + t5.z) + W3 * (t0.z + t6.z);
            r.w = W0 * t3.w + W1 * (t2.w + t4.w) + W2 * (t1.w + t5.w) + W3 * (t0.w + t6.w);
            *(float4*)(outp + (ty0 + oy) * 128 + tx0 + ox) = r;
        }
    }

    // ======================= phase B : |curl v| halo ======================
    {
        const float* pu = v + (size_t)(n * 3 + 0) * VOL + z * S2D;
        const float* pv = v + (size_t)(n * 3 + 1) * VOL + z * S2D;
        const float* pw = v + (size_t)(n * 3 + 2) * VOL + z * S2D;
        const int   dzo = (z < 127) ? S2D : -S2D;
        const float ez  = (z < 127) ? 1.f : -1.f;

        for (int i = tid; i < LDY * NQ; i += 256) {
            int ly = i / NQ, q = i - ly * NQ;
            int gy = ty0 + ly - 3, gx = tx0 + q * 4 - 4;
            float4 val = F4Z;
            if ((unsigned)gy < 128u && (unsigned)gx < 128u) {
                int   o   = gy * 128 + gx;
                int   dyo = (gy < 127) ? 128 : -128;
                float ey  = (gy < 127) ? 1.f : -1.f;

                float4 uc = *(const float4*)(pu + o);
                float4 uz = *(const float4*)(pu + o + dzo);
                float4 uy = *(const float4*)(pu + o + dyo);
                float4 vc = *(const float4*)(pv + o);
                float4 vz = *(const float4*)(pv + o + dzo);
                float4 wc = *(const float4*)(pw + o);
                float4 wy = *(const float4*)(pw + o + dyo);
                float vn4 = 0.f, wn4 = 0.f;
                if (gx + 4 < 128) { vn4 = pv[o + 4]; wn4 = pw[o + 4]; }

                // z-derivatives
                float duz0 = ez * (uz.x - uc.x), duz1 = ez * (uz.y - uc.y);
                float duz2 = ez * (uz.z - uc.z), duz3 = ez * (uz.w - uc.w);
                float dvz0 = ez * (vz.x - vc.x), dvz1 = ez * (vz.y - vc.y);
                float dvz2 = ez * (vz.z - vc.z), dvz3 = ez * (vz.w - vc.w);
                // y-derivatives
                float duy0 = ey * (uy.x - uc.x), duy1 = ey * (uy.y - uc.y);
                float duy2 = ey * (uy.z - uc.z), duy3 = ey * (uy.w - uc.w);
                float dwy0 = ey * (wy.x - wc.x), dwy1 = ey * (wy.y - wc.y);
                float dwy2 = ey * (wy.z - wc.z), dwy3 = ey * (wy.w - wc.w);
                // x-derivatives (quad-internal; .w uses neighbor or clamp)
                float dvx0 = vc.y - vc.x, dvx1 = vc.z - vc.y, dvx2 = vc.w - vc.z;
                float dwx0 = wc.y - wc.x, dwx1 = wc.z - wc.y, dwx2 = wc.w - wc.z;
                float dvx3, dwx3;
                if (gx + 3 < 127) { dvx3 = vn4 - vc.w;  dwx3 = wn4 - wc.w; }
                else              { dvx3 = vc.w - vc.z; dwx3 = wc.w - wc.z; }

                float cu0 = dwy0 - dvz0, cv0 = duz0 - dwx0, cw0 = dvx0 - duy0;
                float cu1 = dwy1 - dvz1, cv1 = duz1 - dwx1, cw1 = dvx1 - duy1;
                float cu2 = dwy2 - dvz2, cv2 = duz2 - dwx2, cw2 = dvx2 - duy2;
                float cu3 = dwy3 - dvz3, cv3 = duz3 - dwx3, cw3 = dvx3 - duy3;
                val.x = sqrtf(cu0 * cu0 + cv0 * cv0 + cw0 * cw0);
                val.y = sqrtf(cu1 * cu1 + cv1 * cv1 + cw1 * cw1);
                val.z = sqrtf(cu2 * cu2 + cv2 * cv2 + cw2 * cw2);
                val.w = sqrtf(cu3 * cu3 + cv3 * cv3 + cw3 * cw3);
            }
            *(float4*)&s_in[ly][q * 4] = val;
        }
    }
    __syncthreads();   // covers y-pass-A s_tmp reads AND B halo writes

    for (int i = tid; i < LDY * 16; i += 256) {
        int ly = i >> 4, ox = (i & 15) * 4;
        float4 a = *(const float4*)&s_in[ly][ox];
        float4 b = *(const float4*)&s_in[ly][ox + 4];
        float4 c = *(const float4*)&s_in[ly][ox + 8];
        float4 r;
        r.x = W0 * b.x + W1 * (a.w + b.y) + W2 * (a.z + b.z) + W3 * (a.y + b.w);
        r.y = W0 * b.y + W1 * (b.x + b.z) + W2 * (a.w + b.w) + W3 * (a.z + c.x);
        r.z = W0 * b.z + W1 * (b.y + b.w) + W2 * (b.x + c.x) + W3 * (a.w + c.y);
        r.w = W0 * b.w + W1 * (b.z + c.x) + W2 * (b.y + c.y) + W3 * (b.x + c.z);
        *(float4*)&s_tmp[ly][ox] = r;
    }
    __syncthreads();

    {
        float* outp = g_b + (size_t)n * VOL + z * S2D;
        for (int i = tid; i < TSY * 16; i += 256) {
            int oy = i >> 4, ox = (i & 15) * 4;
            float4 t0 = *(const float4*)&s_tmp[oy    ][ox];
            float4 t1 = *(const float4*)&s_tmp[oy + 1][ox];
            float4 t2 = *(const float4*)&s_tmp[oy + 2][ox];
            float4 t3 = *(const float4*)&s_tmp[oy + 3][ox];
            float4 t4 = *(const float4*)&s_tmp[oy + 4][ox];
            float4 t5 = *(const float4*)&s_tmp[oy + 5][ox];
            float4 t6 = *(const float4*)&s_tmp[oy + 6][ox];
            float4 r;
            r.x = W0 * t3.x + W1 * (t2.x + t4.x) + W2 * (t1.x + t5.x) + W3 * (t0.x + t6.x);
            r.y = W0 * t3.y + W1 * (t2.y + t4.y) + W2 * (t1.y + t5.y) + W3 * (t0.y + t6.y);
            r.z = W0 * t3.z + W1 * (t2.z + t4.z) + W2 * (t1.z + t5.z) + W3 * (t0.z + t6.z);
            r.w = W0 * t3.w + W1 * (t2.w + t4.w) + W2 * (t1.w + t5.w) + W3 * (t0.w + t6.w);
            *(float4*)(outp + (ty0 + oy) * 128 + tx0 + ox) = r;
        }
    }
}

// ---------------------------------------------------------------------------
// Integrate kernel: fused Z-smooth + flip + cumsum + transform + trapezoid
// + clip, with shared-memory staging (unchanged from R5; 25.8us).
// Block = 32 columns x 8 chunks (16 zf-steps each) = 256 threads.
// ---------------------------------------------------------------------------
__global__ __launch_bounds__(256)
void integrate_kernel(float* __restrict__ out) {
    __shared__ float sA[128][32];
    __shared__ float sB[128][32];
    __shared__ float s_sum[8][32];
    __shared__ float s_iv [8][32];

    int tid   = threadIdx.x;
    int cl    = tid & 31;                    // column within block
    int chunk = tid >> 5;                    // 0..7 (one warp per chunk)

    int colg0 = blockIdx.x * 32;
    int n   = colg0 >> 14;
    int yx0 = colg0 & 16383;                 // 16384 % 32 == 0: no n straddle

    const float* Abase = g_a + (size_t)n * VOL + yx0;
    const float* Bbase = g_b + (size_t)n * VOL + yx0;

    // ---------------- Phase 0: stage columns ------------------------------
    for (int i = tid; i < 128 * 8; i += 256) {      // 8 float4 per z-row
        int z = i >> 3, c4 = (i & 7) << 2;
        *(float4*)&sA[z][c4] = *(const float4*)(Abase + z * S2D + c4);
        *(float4*)&sB[z][c4] = *(const float4*)(Bbase + z * S2D + c4);
    }
    __syncthreads();

    const int z0 = 127 - 16 * chunk;         // first z of this chunk (walk down)

    // ---------------- Phase 1: chunk-local sum of smoothed ds -------------
    float a[7];
#pragma unroll
    for (int k = 0; k < 7; k++) {
        int zi = z0 + k - 3;
        a[k] = ((unsigned)zi < 128u) ? sA[zi][cl] : 0.f;
    }
    float S = 0.f;
    {
        int z = z0;
#pragma unroll
        for (int i = 0; i < 16; i++) {
            int pz = z - 4;
            float na = (pz >= 0) ? sA[pz][cl] : 0.f;
            S += W0 * a[3] + W1 * (a[2] + a[4])
               + W2 * (a[1] + a[5]) + W3 * (a[0] + a[6]);
#pragma unroll
            for (int k = 6; k >= 1; k--) a[k] = a[k - 1];
            a[0] = na;
            z--;
        }
    }
    s_sum[chunk][cl] = S;
    __syncthreads();

    float Xoff = 0.f;
#pragma unroll
    for (int c = 0; c < 7; c++)
        if (c < chunk) Xoff += s_sum[c][cl];

    // ---------------- Boundary state for chunk > 0 ------------------------
    float tprev = 0.f, vprev = 0.f;
    if (chunk > 0) {
        int zb = z0 + 1;   // z at zf = 16*chunk - 1; taps all in [0,127]
        vprev = W0 * sB[zb][cl]
              + W1 * (sB[zb - 1][cl] + sB[zb + 1][cl])
              + W2 * (sB[zb - 2][cl] + sB[zb + 2][cl])
              + W3 * (sB[zb - 3][cl] + sB[zb + 3][cl]);
        tprev = (Xoff * 20.f + 1.f) * __expf(-20.f * Xoff);
    }

    // ---------------- Phase 2: full evaluation ----------------------------
    float b[7];
#pragma unroll
    for (int k = 0; k < 7; k++) {
        int zi = z0 + k - 3;
        if ((unsigned)zi < 128u) {
            a[k] = sA[zi][cl];
            b[k] = sB[zi][cl];
        } else {
            a[k] = 0.f; b[k] = 0.f;
        }
    }

    float xacc = Xoff, iv = 0.f;
    int z = z0;
#pragma unroll
    for (int i = 0; i < 16; i++) {
        int pz = z - 4;
        float na = 0.f, nb = 0.f;
        if (pz >= 0) { na = sA[pz][cl]; nb = sB[pz][cl]; }

        float ds_s = W0 * a[3] + W1 * (a[2] + a[4])
                   + W2 * (a[1] + a[5]) + W3 * (a[0] + a[6]);
        float vn_s = W0 * b[3] + W1 * (b[2] + b[4])
                   + W2 * (b[1] + b[5]) + W3 * (b[0] + b[6]);

        xacc += ds_s;
        float tt = (xacc * 20.f + 1.f) * __expf(-20.f * xacc);

        if (i == 0 && chunk == 0)
            iv = (1.f - tt) * vn_s;                       // front term
        else
            iv += (tprev - tt) * (vprev + vn_s) * 0.5f;   // trapezoid
        tprev = tt; vprev = vn_s;

#pragma unroll
        for (int k = 6; k >= 1; k--) { a[k] = a[k - 1]; b[k] = b[k - 1]; }
        a[0] = na; b[0] = nb;
        z--;
    }

    s_iv[chunk][cl] = iv;
    __syncthreads();

    if (chunk == 0) {
        float tot = iv;
#pragma unroll
        for (int c = 1; c < 8; c++) tot += s_iv[c][cl];
        out[colg0 + cl] = fminf(fmaxf(tot, 0.f), 1.f);
    }
}

// ---------------------------------------------------------------------------
extern "C" void kernel_launch(void* const* d_in, const int* in_sizes, int n_in,
                              void* d_out, int out_size) {
    const float* d = (const float*)d_in[0];
    const float* v = (const float*)d_in[1];
    if (in_sizes[0] > in_sizes[1]) {   // safety: d is the smaller tensor
        const float* tmp = d; d = v; v = tmp;
    }
    float* out = (float*)d_out;

    dim3 g2(128 / TSX, 128 / TSY, NB * 128);
    fused_smooth_kernel<<<g2, 256>>>(d, v);   // g_a (d) and g_b (|curl v|)

    integrate_kernel<<<65536 / 32, 256>>>(out);
}

// round 9
// speedup vs baseline: 1.5914x; 1.0635x over previous
#include <cuda_runtime.h>
#include <math.h>

#define VOL   2097152              // 128^3
#define NB    4
#define S2D   16384                // 128*128 (z stride)

// Normalized 1-D Gaussian weights (sigma=1.6, 7 taps), sum = 1.
#define W0 0.25603832f   // center
#define W1 0.21061137f   // +-1
#define W2 0.11722290f   // +-2
#define W3 0.04414655f   // +-3

// Scratch (allocation-free contract: __device__ globals)
__device__ float g_a [(size_t)NB * VOL];   // d   smoothed in x,y
__device__ float g_b [(size_t)NB * VOL];   // |curl v| smoothed in x,y

#define TSX 64
#define TSY 32
#define LDY 38   // TSY + 6 (y halo rows)
#define NQ  18   // quads per halo row: covers gx in [tx0-4, tx0+68)
#define SPX 72   // NQ*4 floats per smem row (288B, 16B-multiple)

#define F4Z make_float4(0.f, 0.f, 0.f, 0.f)

// y-pass for one quad column: 4 outputs from a 10-row register window.
// itm in [0,128): quad = itm&15, ystrip = itm>>4 (4 oy per strip).
__device__ __forceinline__ void ypass_store(const float (*s_tmp)[TSX],
                                            float* outp, int ty0, int tx0,
                                            int itm) {
    int ox = (itm & 15) * 4;
    int oy = (itm >> 4) * 4;
    float4 t[10];
#pragma unroll
    for (int r = 0; r < 10; r++)
        t[r] = *(const float4*)&s_tmp[oy + r][ox];
#pragma unroll
    for (int j = 0; j < 4; j++) {
        float4 r4;
        r4.x = W0 * t[j+3].x + W1 * (t[j+2].x + t[j+4].x)
             + W2 * (t[j+1].x + t[j+5].x) + W3 * (t[j].x + t[j+6].x);
        r4.y = W0 * t[j+3].y + W1 * (t[j+2].y + t[j+4].y)
             + W2 * (t[j+1].y + t[j+5].y) + W3 * (t[j].y + t[j+6].y);
        r4.z = W0 * t[j+3].z + W1 * (t[j+2].z + t[j+4].z)
             + W2 * (t[j+1].z + t[j+5].z) + W3 * (t[j].z + t[j+6].z);
        r4.w = W0 * t[j+3].w + W1 * (t[j+2].w + t[j+4].w)
             + W2 * (t[j+1].w + t[j+5].w) + W3 * (t[j].w + t[j+6].w);
        *(float4*)(outp + (ty0 + oy + j) * 128 + tx0 + ox) = r4;
    }
}

// ---------------------------------------------------------------------------
// Fused kernel (vectorized tiles, strip-mined y-pass):
//   phase A: d  -> separable X,Y smooth -> g_a
//   phase B: |curl v| -> separable X,Y smooth -> g_b
// Halo x-range [tx0-4, tx0+68) = 18 four-aligned quads, each fully in range
// or fully out (tx0 multiple of 64), so every access is float4.
// fdiff clamp via diff = e*(f[o+delta]-f[o]) with (delta,e) flipped at i==127.
// Convolution zero-pads outside the 128x128 slice.
//
// Sync correctness: the single __syncthreads() after the phase-B halo loop
// orders (a) y-pass-A s_tmp reads before phase-B x-pass s_tmp writes and
// (b) phase-B s_in writes before phase-B x-pass s_in reads. No barrier may
// live inside the halo loop (trip count is thread-dependent).
// ---------------------------------------------------------------------------
__global__ __launch_bounds__(256)
void fused_smooth_kernel(const float* __restrict__ d,
                         const float* __restrict__ v) {
    int nz = blockIdx.z;             // n*128 + z
    int n = nz >> 7, z = nz & 127;
    int tx0 = blockIdx.x * TSX;
    int ty0 = blockIdx.y * TSY;

    __shared__ __align__(16) float s_in [LDY][SPX];
    __shared__ __align__(16) float s_tmp[LDY][TSX];

    int tid = threadIdx.x;

    // ======================= phase A : smooth(d) =========================
    {
        const float* slice = d + (size_t)n * VOL + z * S2D;
        for (int i = tid; i < LDY * NQ; i += 256) {
            int ly = i / NQ, q = i - ly * NQ;
            int gy = ty0 + ly - 3, gx = tx0 + q * 4 - 4;
            float4 val = F4Z;
            if ((unsigned)gy < 128u && (unsigned)gx < 128u)   // gx 4-aligned
                val = *(const float4*)(slice + gy * 128 + gx);
            *(float4*)&s_in[ly][q * 4] = val;
        }
    }
    __syncthreads();

    // x-pass: 3 aligned LDS.128 per 4 outputs
    for (int i = tid; i < LDY * 16; i += 256) {
        int ly = i >> 4, ox = (i & 15) * 4;
        float4 a = *(const float4*)&s_in[ly][ox];
        float4 b = *(const float4*)&s_in[ly][ox + 4];
        float4 c = *(const float4*)&s_in[ly][ox + 8];
        float4 r;
        r.x = W0 * b.x + W1 * (a.w + b.y) + W2 * (a.z + b.z) + W3 * (a.y + b.w);
        r.y = W0 * b.y + W1 * (b.x + b.z) + W2 * (a.w + b.w) + W3 * (a.z + c.x);
        r.z = W0 * b.z + W1 * (b.y + b.w) + W2 * (b.x + c.x) + W3 * (a.w + c.y);
        r.w = W0 * b.w + W1 * (b.z + c.x) + W2 * (b.y + c.y) + W3 * (b.x + c.z);
        *(float4*)&s_tmp[ly][ox] = r;
    }
    __syncthreads();

    // y-pass + store (strip-mined: 128 items, 16 outputs each).
    // Threads >= 128 fall through into the phase-B halo loop immediately;
    // that loop writes only s_in, which is idle here — safe overlap.
    {
        float* outp = g_a + (size_t)n * VOL + z * S2D;
        if (tid < 128) ypass_store(s_tmp, outp, ty0, tx0, tid);
    }

    // ======================= phase B : |curl v| halo ======================
    {
        const float* pu = v + (size_t)(n * 3 + 0) * VOL + z * S2D;
        const float* pv = v + (size_t)(n * 3 + 1) * VOL + z * S2D;
        const float* pw = v + (size_t)(n * 3 + 2) * VOL + z * S2D;
        const int   dzo = (z < 127) ? S2D : -S2D;
        const float ez  = (z < 127) ? 1.f : -1.f;

        for (int i = tid; i < LDY * NQ; i += 256) {
            int ly = i / NQ, q = i - ly * NQ;
            int gy = ty0 + ly - 3, gx = tx0 + q * 4 - 4;
            float4 val = F4Z;
            if ((unsigned)gy < 128u && (unsigned)gx < 128u) {
                int   o   = gy * 128 + gx;
                int   dyo = (gy < 127) ? 128 : -128;
                float ey  = (gy < 127) ? 1.f : -1.f;

                float4 uc = *(const float4*)(pu + o);
                float4 uz = *(const float4*)(pu + o + dzo);
                float4 uy = *(const float4*)(pu + o + dyo);
                float4 vc = *(const float4*)(pv + o);
                float4 vz = *(const float4*)(pv + o + dzo);
                float4 wc = *(const float4*)(pw + o);
                float4 wy = *(const float4*)(pw + o + dyo);
                float vn4 = 0.f, wn4 = 0.f;
                if (gx + 4 < 128) { vn4 = pv[o + 4]; wn4 = pw[o + 4]; }

                // z-derivatives
                float duz0 = ez * (uz.x - uc.x), duz1 = ez * (uz.y - uc.y);
                float duz2 = ez * (uz.z - uc.z), duz3 = ez * (uz.w - uc.w);
                float dvz0 = ez * (vz.x - vc.x), dvz1 = ez * (vz.y - vc.y);
                float dvz2 = ez * (vz.z - vc.z), dvz3 = ez * (vz.w - vc.w);
                // y-derivatives
                float duy0 = ey * (uy.x - uc.x), duy1 = ey * (uy.y - uc.y);
                float duy2 = ey * (uy.z - uc.z), duy3 = ey * (uy.w - uc.w);
                float dwy0 = ey * (wy.x - wc.x), dwy1 = ey * (wy.y - wc.y);
                float dwy2 = ey * (wy.z - wc.z), dwy3 = ey * (wy.w - wc.w);
                // x-derivatives (quad-internal; .w uses neighbor or clamp)
                float dvx0 = vc.y - vc.x, dvx1 = vc.z - vc.y, dvx2 = vc.w - vc.z;
                float dwx0 = wc.y - wc.x, dwx1 = wc.z - wc.y, dwx2 = wc.w - wc.z;
                float dvx3, dwx3;
                if (gx + 3 < 127) { dvx3 = vn4 - vc.w;  dwx3 = wn4 - wc.w; }
                else              { dvx3 = vc.w - vc.z; dwx3 = wc.w - wc.z; }

                float cu0 = dwy0 - dvz0, cv0 = duz0 - dwx0, cw0 = dvx0 - duy0;
                float cu1 = dwy1 - dvz1, cv1 = duz1 - dwx1, cw1 = dvx1 - duy1;
                float cu2 = dwy2 - dvz2, cv2 = duz2 - dwx2, cw2 = dvx2 - duy2;
                float cu3 = dwy3 - dvz3, cv3 = duz3 - dwx3, cw3 = dvx3 - duy3;
                val.x = sqrtf(cu0 * cu0 + cv0 * cv0 + cw0 * cw0);
                val.y = sqrtf(cu1 * cu1 + cv1 * cv1 + cw1 * cw1);
                val.z = sqrtf(cu2 * cu2 + cv2 * cv2 + cw2 * cw2);
                val.w = sqrtf(cu3 * cu3 + cv3 * cv3 + cw3 * cw3);
            }
            *(float4*)&s_in[ly][q * 4] = val;
        }
    }
    __syncthreads();   // orders y-pass-A s_tmp reads & halo-B s_in writes

    for (int i = tid; i < LDY * 16; i += 256) {
        int ly = i >> 4, ox = (i & 15) * 4;
        float4 a = *(const float4*)&s_in[ly][ox];
        float4 b = *(const float4*)&s_in[ly][ox + 4];
        float4 c = *(const float4*)&s_in[ly][ox + 8];
        float4 r;
        r.x = W0 * b.x + W1 * (a.w + b.y) + W2 * (a.z + b.z) + W3 * (a.y + b.w);
        r.y = W0 * b.y + W1 * (b.x + b.z) + W2 * (a.w + b.w) + W3 * (a.z + c.x);
        r.z = W0 * b.z + W1 * (b.y + b.w) + W2 * (b.x + c.x) + W3 * (a.w + c.y);
        r.w = W0 * b.w + W1 * (b.z + c.x) + W2 * (b.y + c.y) + W3 * (b.x + c.z);
        *(float4*)&s_tmp[ly][ox] = r;
    }
    __syncthreads();

    {
        float* outp = g_b + (size_t)n * VOL + z * S2D;
        if (tid < 128) ypass_store(s_tmp, outp, ty0, tx0, tid);
    }
}

// ---------------------------------------------------------------------------
// Integrate kernel: fused Z-smooth + flip + cumsum + transform + trapezoid
// + clip, with shared-memory staging (unchanged; ~26us).
// Block = 32 columns x 8 chunks (16 zf-steps each) = 256 threads.
// ---------------------------------------------------------------------------
__global__ __launch_bounds__(256)
void integrate_kernel(float* __restrict__ out) {
    __shared__ float sA[128][32];
    __shared__ float sB[128][32];
    __shared__ float s_sum[8][32];
    __shared__ float s_iv [8][32];

    int tid   = threadIdx.x;
    int cl    = tid & 31;                    // column within block
    int chunk = tid >> 5;                    // 0..7 (one warp per chunk)

    int colg0 = blockIdx.x * 32;
    int n   = colg0 >> 14;
    int yx0 = colg0 & 16383;                 // 16384 % 32 == 0: no n straddle

    const float* Abase = g_a + (size_t)n * VOL + yx0;
    const float* Bbase = g_b + (size_t)n * VOL + yx0;

    // ---------------- Phase 0: stage columns ------------------------------
    for (int i = tid; i < 128 * 8; i += 256) {      // 8 float4 per z-row
        int z = i >> 3, c4 = (i & 7) << 2;
        *(float4*)&sA[z][c4] = *(const float4*)(Abase + z * S2D + c4);
        *(float4*)&sB[z][c4] = *(const float4*)(Bbase + z * S2D + c4);
    }
    __syncthreads();

    const int z0 = 127 - 16 * chunk;         // first z of this chunk (walk down)

    // ---------------- Phase 1: chunk-local sum of smoothed ds -------------
    float a[7];
#pragma unroll
    for (int k = 0; k < 7; k++) {
        int zi = z0 + k - 3;
        a[k] = ((unsigned)zi < 128u) ? sA[zi][cl] : 0.f;
    }
    float S = 0.f;
    {
        int z = z0;
#pragma unroll
        for (int i = 0; i < 16; i++) {
            int pz = z - 4;
            float na = (pz >= 0) ? sA[pz][cl] : 0.f;
            S += W0 * a[3] + W1 * (a[2] + a[4])
               + W2 * (a[1] + a[5]) + W3 * (a[0] + a[6]);
#pragma unroll
            for (int k = 6; k >= 1; k--) a[k] = a[k - 1];
            a[0] = na;
            z--;
        }
    }
    s_sum[chunk][cl] = S;
    __syncthreads();

    float Xoff = 0.f;
#pragma unroll
    for (int c = 0; c < 7; c++)
        if (c < chunk) Xoff += s_sum[c][cl];

    // ---------------- Boundary state for chunk > 0 ------------------------
    float tprev = 0.f, vprev = 0.f;
    if (chunk > 0) {
        int zb = z0 + 1;   // z at zf = 16*chunk - 1; taps all in [0,127]
        vprev = W0 * sB[zb][cl]
              + W1 * (sB[zb - 1][cl] + sB[zb + 1][cl])
              + W2 * (sB[zb - 2][cl] + sB[zb + 2][cl])
              + W3 * (sB[zb - 3][cl] + sB[zb + 3][cl]);
        tprev = (Xoff * 20.f + 1.f) * __expf(-20.f * Xoff);
    }

    // ---------------- Phase 2: full evaluation ----------------------------
    float b[7];
#pragma unroll
    for (int k = 0; k < 7; k++) {
        int zi = z0 + k - 3;
        if ((unsigned)zi < 128u) {
            a[k] = sA[zi][cl];
            b[k] = sB[zi][cl];
        } else {
            a[k] = 0.f; b[k] = 0.f;
        }
    }

    float xacc = Xoff, iv = 0.f;
    int z = z0;
#pragma unroll
    for (int i = 0; i < 16; i++) {
        int pz = z - 4;
        float na = 0.f, nb = 0.f;
        if (pz >= 0) { na = sA[pz][cl]; nb = sB[pz][cl]; }

        float ds_s = W0 * a[3] + W1 * (a[2] + a[4])
                   + W2 * (a[1] + a[5]) + W3 * (a[0] + a[6]);
        float vn_s = W0 * b[3] + W1 * (b[2] + b[4])
                   + W2 * (b[1] + b[5]) + W3 * (b[0] + b[6]);

        xacc += ds_s;
        float tt = (xacc * 20.f + 1.f) * __expf(-20.f * xacc);

        if (i == 0 && chunk == 0)
            iv = (1.f - tt) * vn_s;                       // front term
        else
            iv += (tprev - tt) * (vprev + vn_s) * 0.5f;   // trapezoid
        tprev = tt; vprev = vn_s;

#pragma unroll
        for (int k = 6; k >= 1; k--) { a[k] = a[k - 1]; b[k] = b[k - 1]; }
        a[0] = na; b[0] = nb;
        z--;
    }

    s_iv[chunk][cl] = iv;
    __syncthreads();

    if (chunk == 0) {
        float tot = iv;
#pragma unroll
        for (int c = 1; c < 8; c++) tot += s_iv[c][cl];
        out[colg0 + cl] = fminf(fmaxf(tot, 0.f), 1.f);
    }
}

// ---------------------------------------------------------------------------
extern "C" void kernel_launch(void* const* d_in, const int* in_sizes, int n_in,
                              void* d_out, int out_size) {
    const float* d = (const float*)d_in[0];
    const float* v = (const float*)d_in[1];
    if (in_sizes[0] > in_sizes[1]) {   // safety: d is the smaller tensor
        const float* tmp = d; d = v; v = tmp;
    }
    float* out = (float*)d_out;

    dim3 g2(128 / TSX, 128 / TSY, NB * 128);
    fused_smooth_kernel<<<g2, 256>>>(d, v);   // g_a (d) and g_b (|curl v|)

    integrate_kernel<<<65536 / 32, 256>>>(out);
}

// round 10
// speedup vs baseline: 1.6950x; 1.0651x over previous
#include <cuda_runtime.h>
#include <math.h>

#define VOL   2097152              // 128^3
#define NB    4
#define S2D   16384                // 128*128 (z stride)

// Normalized 1-D Gaussian weights (sigma=1.6, 7 taps), sum = 1.
#define W0 0.25603832f   // center
#define W1 0.21061137f   // +-1
#define W2 0.11722290f   // +-2
#define W3 0.04414655f   // +-3

// Scratch (allocation-free contract: __device__ globals)
__device__ float g_a [(size_t)NB * VOL];   // d   smoothed in x,y
__device__ float g_b [(size_t)NB * VOL];   // |curl v| smoothed in x,y

#define TSY 32
#define LDY 38    // TSY + 6 (y halo rows)
#define NQB 34    // phase-B halo quads per row: gx in [-4, 132)
#define SIN 140   // s_in row stride (floats): 136 data + 4 pad (560B, 16B mult)

#define F4Z make_float4(0.f, 0.f, 0.f, 0.f)

// 7-tap x-conv of a 4-wide output quad from three f4 windows:
// a = values at ox-4.., b = ox.., c = ox+4..
__device__ __forceinline__ float4 xconv(float4 a, float4 b, float4 c) {
    float4 r;
    r.x = W0 * b.x + W1 * (a.w + b.y) + W2 * (a.z + b.z) + W3 * (a.y + b.w);
    r.y = W0 * b.y + W1 * (b.x + b.z) + W2 * (a.w + b.w) + W3 * (a.z + c.x);
    r.z = W0 * b.z + W1 * (b.y + b.w) + W2 * (b.x + c.x) + W3 * (a.w + c.y);
    r.w = W0 * b.w + W1 * (b.z + c.x) + W2 * (b.y + c.y) + W3 * (b.x + c.z);
    return r;
}

// y-pass: one output quad column x 4 rows from a 10-row register window.
// itm in [0,256): ox = (itm&31)*4, oy = (itm>>5)*4.
__device__ __forceinline__ void ypass_store(const float (*s_tmp)[128],
                                            float* outp, int ty0, int itm) {
    int ox = (itm & 31) * 4;
    int oy = (itm >> 5) * 4;
    float4 t[10];
#pragma unroll
    for (int r = 0; r < 10; r++)
        t[r] = *(const float4*)&s_tmp[oy + r][ox];
#pragma unroll
    for (int j = 0; j < 4; j++) {
        float4 r4;
        r4.x = W0 * t[j+3].x + W1 * (t[j+2].x + t[j+4].x)
             + W2 * (t[j+1].x + t[j+5].x) + W3 * (t[j].x + t[j+6].x);
        r4.y = W0 * t[j+3].y + W1 * (t[j+2].y + t[j+4].y)
             + W2 * (t[j+1].y + t[j+5].y) + W3 * (t[j].y + t[j+6].y);
        r4.z = W0 * t[j+3].z + W1 * (t[j+2].z + t[j+4].z)
             + W2 * (t[j+1].z + t[j+5].z) + W3 * (t[j].z + t[j+6].z);
        r4.w = W0 * t[j+3].w + W1 * (t[j+2].w + t[j+4].w)
             + W2 * (t[j+1].w + t[j+5].w) + W3 * (t[j].w + t[j+6].w);
        *(float4*)(outp + (ty0 + oy + j) * 128 + ox) = r4;
    }
}

// ---------------------------------------------------------------------------
// Fused kernel, full-width 128x32 tiles:
//   phase A: d -> x-conv DIRECTLY from global (no staging) -> s_tmp -> y-pass -> g_a
//   phase B: |curl v| halo -> s_in -> x-pass -> s_tmp -> y-pass -> g_b
// fdiff clamp via diff = e*(f[o+delta]-f[o]) with (delta,e) flipped at i==127.
// Convolution zero-pads outside the 128x128 slice.
// Sync ordering: [A x-pass] sync [A y-pass (s_tmp reads) || B halo (s_in
// writes)] sync [B x-pass] sync [B y-pass]. No barrier inside the halo loop
// (its trip count is thread-dependent).
// ---------------------------------------------------------------------------
__global__ __launch_bounds__(256)
void fused_smooth_kernel(const float* __restrict__ d,
                         const float* __restrict__ v) {
    int ty0 = blockIdx.x * TSY;
    int nz  = blockIdx.y;            // n*128 + z
    int n = nz >> 7, z = nz & 127;

    __shared__ __align__(16) float s_in [LDY][SIN];
    __shared__ __align__(16) float s_tmp[LDY][128];

    int tid = threadIdx.x;

    // ============ phase A : x-conv of d straight from global =============
    {
        const float* slice = d + (size_t)n * VOL + z * S2D;
        for (int i = tid; i < LDY * 32; i += 256) {
            int ly = i >> 5, qx = i & 31;
            int gy = ty0 + ly - 3, ox = qx * 4;
            float4 a = F4Z, b = F4Z, c = F4Z;
            if ((unsigned)gy < 128u) {
                const float* row = slice + gy * 128;
                if (qx >= 1)  a = *(const float4*)(row + ox - 4);
                b = *(const float4*)(row + ox);
                if (qx <= 30) c = *(const float4*)(row + ox + 4);
            }
            *(float4*)&s_tmp[ly][ox] = xconv(a, b, c);
        }
    }
    __syncthreads();

    // A y-pass (reads s_tmp only) — overlaps with phase-B halo (writes s_in)
    ypass_store(s_tmp, g_a + (size_t)n * VOL + z * S2D, ty0, tid);

    // ======================= phase B : |curl v| halo ======================
    {
        const float* pu = v + (size_t)(n * 3 + 0) * VOL + z * S2D;
        const float* pv = v + (size_t)(n * 3 + 1) * VOL + z * S2D;
        const float* pw = v + (size_t)(n * 3 + 2) * VOL + z * S2D;
        const int   dzo = (z < 127) ? S2D : -S2D;
        const float ez  = (z < 127) ? 1.f : -1.f;

        for (int i = tid; i < LDY * NQB; i += 256) {
            int ly = i / NQB, q = i - ly * NQB;
            int gy = ty0 + ly - 3, gx = q * 4 - 4;
            float4 val = F4Z;
            if ((unsigned)gy < 128u && (unsigned)gx < 128u) {
                int   o   = gy * 128 + gx;
                int   dyo = (gy < 127) ? 128 : -128;
                float ey  = (gy < 127) ? 1.f : -1.f;

                float4 uc = *(const float4*)(pu + o);
                float4 uz = *(const float4*)(pu + o + dzo);
                float4 uy = *(const float4*)(pu + o + dyo);
                float4 vc = *(const float4*)(pv + o);
                float4 vz = *(const float4*)(pv + o + dzo);
                float4 wc = *(const float4*)(pw + o);
                float4 wy = *(const float4*)(pw + o + dyo);
                float vn4 = 0.f, wn4 = 0.f;
                if (gx + 4 < 128) { vn4 = pv[o + 4]; wn4 = pw[o + 4]; }

                // z-derivatives
                float duz0 = ez * (uz.x - uc.x), duz1 = ez * (uz.y - uc.y);
                float duz2 = ez * (uz.z - uc.z), duz3 = ez * (uz.w - uc.w);
                float dvz0 = ez * (vz.x - vc.x), dvz1 = ez * (vz.y - vc.y);
                float dvz2 = ez * (vz.z - vc.z), dvz3 = ez * (vz.w - vc.w);
                // y-derivatives
                float duy0 = ey * (uy.x - uc.x), duy1 = ey * (uy.y - uc.y);
                float duy2 = ey * (uy.z - uc.z), duy3 = ey * (uy.w - uc.w);
                float dwy0 = ey * (wy.x - wc.x), dwy1 = ey * (wy.y - wc.y);
                float dwy2 = ey * (wy.z - wc.z), dwy3 = ey * (wy.w - wc.w);
                // x-derivatives (quad-internal; .w uses neighbor or clamp)
                float dvx0 = vc.y - vc.x, dvx1 = vc.z - vc.y, dvx2 = vc.w - vc.z;
                float dwx0 = wc.y - wc.x, dwx1 = wc.z - wc.y, dwx2 = wc.w - wc.z;
                float dvx3, dwx3;
                if (gx + 3 < 127) { dvx3 = vn4 - vc.w;  dwx3 = wn4 - wc.w; }
                else              { dvx3 = vc.w - vc.z; dwx3 = wc.w - wc.z; }

                float cu0 = dwy0 - dvz0, cv0 = duz0 - dwx0, cw0 = dvx0 - duy0;
                float cu1 = dwy1 - dvz1, cv1 = duz1 - dwx1, cw1 = dvx1 - duy1;
                float cu2 = dwy2 - dvz2, cv2 = duz2 - dwx2, cw2 = dvx2 - duy2;
                float cu3 = dwy3 - dvz3, cv3 = duz3 - dwx3, cw3 = dvx3 - duy3;
                val.x = sqrtf(cu0 * cu0 + cv0 * cv0 + cw0 * cw0);
                val.y = sqrtf(cu1 * cu1 + cv1 * cv1 + cw1 * cw1);
                val.z = sqrtf(cu2 * cu2 + cv2 * cv2 + cw2 * cw2);
                val.w = sqrtf(cu3 * cu3 + cv3 * cv3 + cw3 * cw3);
            }
            *(float4*)&s_in[ly][q * 4] = val;   // lx = gx + 4
        }
    }
    __syncthreads();   // orders A y-pass s_tmp reads & B halo s_in writes

    // B x-pass: s_in lx = gx+4, so output quad ox reads lx = ox, ox+4, ox+8
    for (int i = tid; i < LDY * 32; i += 256) {
        int ly = i >> 5, ox = (i & 31) * 4;
        float4 a = *(const float4*)&s_in[ly][ox];
        float4 b = *(const float4*)&s_in[ly][ox + 4];
        float4 c = *(const float4*)&s_in[ly][ox + 8];
        *(float4*)&s_tmp[ly][ox] = xconv(a, b, c);
    }
    __syncthreads();

    ypass_store(s_tmp, g_b + (size_t)n * VOL + z * S2D, ty0, tid);
}

// ---------------------------------------------------------------------------
// Integrate kernel: fused Z-smooth + flip + cumsum + transform + trapezoid
// + clip, with shared-memory staging (unchanged; ~26us — protected).
// Block = 32 columns x 8 chunks (16 zf-steps each) = 256 threads.
// ---------------------------------------------------------------------------
__global__ __launch_bounds__(256)
void integrate_kernel(float* __restrict__ out) {
    __shared__ float sA[128][32];
    __shared__ float sB[128][32];
    __shared__ float s_sum[8][32];
    __shared__ float s_iv [8][32];

    int tid   = threadIdx.x;
    int cl    = tid & 31;                    // column within block
    int chunk = tid >> 5;                    // 0..7 (one warp per chunk)

    int colg0 = blockIdx.x * 32;
    int n   = colg0 >> 14;
    int yx0 = colg0 & 16383;                 // 16384 % 32 == 0: no n straddle

    const float* Abase = g_a + (size_t)n * VOL + yx0;
    const float* Bbase = g_b + (size_t)n * VOL + yx0;

    // ---------------- Phase 0: stage columns ------------------------------
    for (int i = tid; i < 128 * 8; i += 256) {      // 8 float4 per z-row
        int z = i >> 3, c4 = (i & 7) << 2;
        *(float4*)&sA[z][c4] = *(const float4*)(Abase + z * S2D + c4);
        *(float4*)&sB[z][c4] = *(const float4*)(Bbase + z * S2D + c4);
    }
    __syncthreads();

    const int z0 = 127 - 16 * chunk;         // first z of this chunk (walk down)

    // ---------------- Phase 1: chunk-local sum of smoothed ds -------------
    float a[7];
#pragma unroll
    for (int k = 0; k < 7; k++) {
        int zi = z0 + k - 3;
        a[k] = ((unsigned)zi < 128u) ? sA[zi][cl] : 0.f;
    }
    float S = 0.f;
    {
        int z = z0;
#pragma unroll
        for (int i = 0; i < 16; i++) {
            int pz = z - 4;
            float na = (pz >= 0) ? sA[pz][cl] : 0.f;
            S += W0 * a[3] + W1 * (a[2] + a[4])
               + W2 * (a[1] + a[5]) + W3 * (a[0] + a[6]);
#pragma unroll
            for (int k = 6; k >= 1; k--) a[k] = a[k - 1];
            a[0] = na;
            z--;
        }
    }
    s_sum[chunk][cl] = S;
    __syncthreads();

    float Xoff = 0.f;
#pragma unroll
    for (int c = 0; c < 7; c++)
        if (c < chunk) Xoff += s_sum[c][cl];

    // ---------------- Boundary state for chunk > 0 ------------------------
    float tprev = 0.f, vprev = 0.f;
    if (chunk > 0) {
        int zb = z0 + 1;   // z at zf = 16*chunk - 1; taps all in [0,127]
        vprev = W0 * sB[zb][cl]
              + W1 * (sB[zb - 1][cl] + sB[zb + 1][cl])
              + W2 * (sB[zb - 2][cl] + sB[zb + 2][cl])
              + W3 * (sB[zb - 3][cl] + sB[zb + 3][cl]);
        tprev = (Xoff * 20.f + 1.f) * __expf(-20.f * Xoff);
    }

    // ---------------- Phase 2: full evaluation ----------------------------
    float b[7];
#pragma unroll
    for (int k = 0; k < 7; k++) {
        int zi = z0 + k - 3;
        if ((unsigned)zi < 128u) {
            a[k] = sA[zi][cl];
            b[k] = sB[zi][cl];
        } else {
            a[k] = 0.f; b[k] = 0.f;
        }
    }

    float xacc = Xoff, iv = 0.f;
    int z = z0;
#pragma unroll
    for (int i = 0; i < 16; i++) {
        int pz = z - 4;
        float na = 0.f, nb = 0.f;
        if (pz >= 0) { na = sA[pz][cl]; nb = sB[pz][cl]; }

        float ds_s = W0 * a[3] + W1 * (a[2] + a[4])
                   + W2 * (a[1] + a[5]) + W3 * (a[0] + a[6]);
        float vn_s = W0 * b[3] + W1 * (b[2] + b[4])
                   + W2 * (b[1] + b[5]) + W3 * (b[0] + b[6]);

        xacc += ds_s;
        float tt = (xacc * 20.f + 1.f) * __expf(-20.f * xacc);

        if (i == 0 && chunk == 0)
            iv = (1.f - tt) * vn_s;                       // front term
        else
            iv += (tprev - tt) * (vprev + vn_s) * 0.5f;   // trapezoid
        tprev = tt; vprev = vn_s;

#pragma unroll
        for (int k = 6; k >= 1; k--) { a[k] = a[k - 1]; b[k] = b[k - 1]; }
        a[0] = na; b[0] = nb;
        z--;
    }

    s_iv[chunk][cl] = iv;
    __syncthreads();

    if (chunk == 0) {
        float tot = iv;
#pragma unroll
        for (int c = 1; c < 8; c++) tot += s_iv[c][cl];
        out[colg0 + cl] = fminf(fmaxf(tot, 0.f), 1.f);
    }
}

// ---------------------------------------------------------------------------
extern "C" void kernel_launch(void* const* d_in, const int* in_sizes, int n_in,
                              void* d_out, int out_size) {
    const float* d = (const float*)d_in[0];
    const float* v = (const float*)d_in[1];
    if (in_sizes[0] > in_sizes[1]) {   // safety: d is the smaller tensor
        const float* tmp = d; d = v; v = tmp;
    }
    float* out = (float*)d_out;

    dim3 g2(128 / TSY, NB * 128);             // (y-tile, n*z)
    fused_smooth_kernel<<<g2, 256>>>(d, v);   // g_a (d) and g_b (|curl v|)

    integrate_kernel<<<65536 / 32, 256>>>(out);
}

// round 11
// speedup vs baseline: 1.7462x; 1.0302x over previous
#include <cuda_runtime.h>
#include <math.h>

#define VOL   2097152              // 128^3
#define NB    4
#define S2D   16384                // 128*128 (z stride)

// Normalized 1-D Gaussian weights (sigma=1.6, 7 taps), sum = 1.
#define W0 0.25603832f   // center
#define W1 0.21061137f   // +-1
#define W2 0.11722290f   // +-2
#define W3 0.04414655f   // +-3

// Scratch (allocation-free contract: __device__ globals)
__device__ float g_a [(size_t)NB * VOL];   // d   smoothed in x,y
__device__ float g_b [(size_t)NB * VOL];   // |curl v| smoothed in x,y

#define TSY 32
#define LDY 38    // TSY + 6 (y halo rows)
#define NQB 34    // phase-B halo quads per row: gx in [-4, 132)
#define SIN 140   // s_in row stride (floats): 136 data + 4 pad (560B, 16B mult)

#define F4Z make_float4(0.f, 0.f, 0.f, 0.f)

// 7-tap x-conv of a 4-wide output quad from three f4 windows:
// a = values at ox-4.., b = ox.., c = ox+4..
__device__ __forceinline__ float4 xconv(float4 a, float4 b, float4 c) {
    float4 r;
    r.x = W0 * b.x + W1 * (a.w + b.y) + W2 * (a.z + b.z) + W3 * (a.y + b.w);
    r.y = W0 * b.y + W1 * (b.x + b.z) + W2 * (a.w + b.w) + W3 * (a.z + c.x);
    r.z = W0 * b.z + W1 * (b.y + b.w) + W2 * (b.x + c.x) + W3 * (a.w + c.y);
    r.w = W0 * b.w + W1 * (b.z + c.x) + W2 * (b.y + c.y) + W3 * (b.x + c.z);
    return r;
}

// y-pass: one output quad column x 4 rows from a 10-row register window.
// itm in [0,256): ox = (itm&31)*4, oy = (itm>>5)*4.
__device__ __forceinline__ void ypass_store(const float (*s_tmp)[128],
                                            float* outp, int ty0, int itm) {
    int ox = (itm & 31) * 4;
    int oy = (itm >> 5) * 4;
    float4 t[10];
#pragma unroll
    for (int r = 0; r < 10; r++)
        t[r] = *(const float4*)&s_tmp[oy + r][ox];
#pragma unroll
    for (int j = 0; j < 4; j++) {
        float4 r4;
        r4.x = W0 * t[j+3].x + W1 * (t[j+2].x + t[j+4].x)
             + W2 * (t[j+1].x + t[j+5].x) + W3 * (t[j].x + t[j+6].x);
        r4.y = W0 * t[j+3].y + W1 * (t[j+2].y + t[j+4].y)
             + W2 * (t[j+1].y + t[j+5].y) + W3 * (t[j].y + t[j+6].y);
        r4.z = W0 * t[j+3].z + W1 * (t[j+2].z + t[j+4].z)
             + W2 * (t[j+1].z + t[j+5].z) + W3 * (t[j].z + t[j+6].z);
        r4.w = W0 * t[j+3].w + W1 * (t[j+2].w + t[j+4].w)
             + W2 * (t[j+1].w + t[j+5].w) + W3 * (t[j].w + t[j+6].w);
        *(float4*)(outp + (ty0 + oy + j) * 128 + ox) = r4;
    }
}

// ---------------------------------------------------------------------------
// Fused kernel, full-width 128x32 tiles (UNCHANGED from R10 — 52.4us):
//   phase A: d -> x-conv DIRECTLY from global (no staging) -> s_tmp -> y-pass -> g_a
//   phase B: |curl v| halo -> s_in -> x-pass -> s_tmp -> y-pass -> g_b
// ---------------------------------------------------------------------------
__global__ __launch_bounds__(256)
void fused_smooth_kernel(const float* __restrict__ d,
                         const float* __restrict__ v) {
    int ty0 = blockIdx.x * TSY;
    int nz  = blockIdx.y;            // n*128 + z
    int n = nz >> 7, z = nz & 127;

    __shared__ __align__(16) float s_in [LDY][SIN];
    __shared__ __align__(16) float s_tmp[LDY][128];

    int tid = threadIdx.x;

    // ============ phase A : x-conv of d straight from global =============
    {
        const float* slice = d + (size_t)n * VOL + z * S2D;
        for (int i = tid; i < LDY * 32; i += 256) {
            int ly = i >> 5, qx = i & 31;
            int gy = ty0 + ly - 3, ox = qx * 4;
            float4 a = F4Z, b = F4Z, c = F4Z;
            if ((unsigned)gy < 128u) {
                const float* row = slice + gy * 128;
                if (qx >= 1)  a = *(const float4*)(row + ox - 4);
                b = *(const float4*)(row + ox);
                if (qx <= 30) c = *(const float4*)(row + ox + 4);
            }
            *(float4*)&s_tmp[ly][ox] = xconv(a, b, c);
        }
    }
    __syncthreads();

    // A y-pass (reads s_tmp only) — overlaps with phase-B halo (writes s_in)
    ypass_store(s_tmp, g_a + (size_t)n * VOL + z * S2D, ty0, tid);

    // ======================= phase B : |curl v| halo ======================
    {
        const float* pu = v + (size_t)(n * 3 + 0) * VOL + z * S2D;
        const float* pv = v + (size_t)(n * 3 + 1) * VOL + z * S2D;
        const float* pw = v + (size_t)(n * 3 + 2) * VOL + z * S2D;
        const int   dzo = (z < 127) ? S2D : -S2D;
        const float ez  = (z < 127) ? 1.f : -1.f;

        for (int i = tid; i < LDY * NQB; i += 256) {
            int ly = i / NQB, q = i - ly * NQB;
            int gy = ty0 + ly - 3, gx = q * 4 - 4;
            float4 val = F4Z;
            if ((unsigned)gy < 128u && (unsigned)gx < 128u) {
                int   o   = gy * 128 + gx;
                int   dyo = (gy < 127) ? 128 : -128;
                float ey  = (gy < 127) ? 1.f : -1.f;

                float4 uc = *(const float4*)(pu + o);
                float4 uz = *(const float4*)(pu + o + dzo);
                float4 uy = *(const float4*)(pu + o + dyo);
                float4 vc = *(const float4*)(pv + o);
                float4 vz = *(const float4*)(pv + o + dzo);
                float4 wc = *(const float4*)(pw + o);
                float4 wy = *(const float4*)(pw + o + dyo);
                float vn4 = 0.f, wn4 = 0.f;
                if (gx + 4 < 128) { vn4 = pv[o + 4]; wn4 = pw[o + 4]; }

                // z-derivatives
                float duz0 = ez * (uz.x - uc.x), duz1 = ez * (uz.y - uc.y);
                float duz2 = ez * (uz.z - uc.z), duz3 = ez * (uz.w - uc.w);
                float dvz0 = ez * (vz.x - vc.x), dvz1 = ez * (vz.y - vc.y);
                float dvz2 = ez * (vz.z - vc.z), dvz3 = ez * (vz.w - vc.w);
                // y-derivatives
                float duy0 = ey * (uy.x - uc.x), duy1 = ey * (uy.y - uc.y);
                float duy2 = ey * (uy.z - uc.z), duy3 = ey * (uy.w - uc.w);
                float dwy0 = ey * (wy.x - wc.x), dwy1 = ey * (wy.y - wc.y);
                float dwy2 = ey * (wy.z - wc.z), dwy3 = ey * (wy.w - wc.w);
                // x-derivatives (quad-internal; .w uses neighbor or clamp)
                float dvx0 = vc.y - vc.x, dvx1 = vc.z - vc.y, dvx2 = vc.w - vc.z;
                float dwx0 = wc.y - wc.x, dwx1 = wc.z - wc.y, dwx2 = wc.w - wc.z;
                float dvx3, dwx3;
                if (gx + 3 < 127) { dvx3 = vn4 - vc.w;  dwx3 = wn4 - wc.w; }
                else              { dvx3 = vc.w - vc.z; dwx3 = wc.w - wc.z; }

                float cu0 = dwy0 - dvz0, cv0 = duz0 - dwx0, cw0 = dvx0 - duy0;
                float cu1 = dwy1 - dvz1, cv1 = duz1 - dwx1, cw1 = dvx1 - duy1;
                float cu2 = dwy2 - dvz2, cv2 = duz2 - dwx2, cw2 = dvx2 - duy2;
                float cu3 = dwy3 - dvz3, cv3 = duz3 - dwx3, cw3 = dvx3 - duy3;
                val.x = sqrtf(cu0 * cu0 + cv0 * cv0 + cw0 * cw0);
                val.y = sqrtf(cu1 * cu1 + cv1 * cv1 + cw1 * cw1);
                val.z = sqrtf(cu2 * cu2 + cv2 * cv2 + cw2 * cw2);
                val.w = sqrtf(cu3 * cu3 + cv3 * cv3 + cw3 * cw3);
            }
            *(float4*)&s_in[ly][q * 4] = val;   // lx = gx + 4
        }
    }
    __syncthreads();   // orders A y-pass s_tmp reads & B halo s_in writes

    // B x-pass: s_in lx = gx+4, so output quad ox reads lx = ox, ox+4, ox+8
    for (int i = tid; i < LDY * 32; i += 256) {
        int ly = i >> 5, ox = (i & 31) * 4;
        float4 a = *(const float4*)&s_in[ly][ox];
        float4 b = *(const float4*)&s_in[ly][ox + 4];
        float4 c = *(const float4*)&s_in[ly][ox + 8];
        *(float4*)&s_tmp[ly][ox] = xconv(a, b, c);
    }
    __syncthreads();

    ypass_store(s_tmp, g_b + (size_t)n * VOL + z * S2D, ty0, tid);
}

// ---------------------------------------------------------------------------
// Integrate kernel: fused Z-smooth + flip + cumsum + transform + trapezoid
// + clip, shared-memory staging, 512 threads = 32 columns x 16 chunks of
// 8 zf-steps. Halved serial chain + full warp-cap occupancy (4 blocks/SM).
// ---------------------------------------------------------------------------
__global__ __launch_bounds__(512)
void integrate_kernel(float* __restrict__ out) {
    __shared__ float sA[128][32];
    __shared__ float sB[128][32];
    __shared__ float s_sum[16][32];
    __shared__ float s_iv [16][32];

    int tid   = threadIdx.x;
    int cl    = tid & 31;                    // column within block
    int chunk = tid >> 5;                    // 0..15 (one warp per chunk)

    int colg0 = blockIdx.x * 32;
    int n   = colg0 >> 14;
    int yx0 = colg0 & 16383;                 // 16384 % 32 == 0: no n straddle

    const float* Abase = g_a + (size_t)n * VOL + yx0;
    const float* Bbase = g_b + (size_t)n * VOL + yx0;

    // ---------------- Phase 0: stage columns ------------------------------
    for (int i = tid; i < 128 * 8; i += 512) {      // 8 float4 per z-row
        int z = i >> 3, c4 = (i & 7) << 2;
        *(float4*)&sA[z][c4] = *(const float4*)(Abase + z * S2D + c4);
        *(float4*)&sB[z][c4] = *(const float4*)(Bbase + z * S2D + c4);
    }
    __syncthreads();

    const int z0 = 127 - 8 * chunk;          // first z of this chunk (walk down)

    // ---------------- Phase 1: chunk-local sum of smoothed ds -------------
    float a[7];
#pragma unroll
    for (int k = 0; k < 7; k++) {
        int zi = z0 + k - 3;
        a[k] = ((unsigned)zi < 128u) ? sA[zi][cl] : 0.f;
    }
    float S = 0.f;
    {
        int z = z0;
#pragma unroll
        for (int i = 0; i < 8; i++) {
            int pz = z - 4;
            float na = (pz >= 0) ? sA[pz][cl] : 0.f;
            S += W0 * a[3] + W1 * (a[2] + a[4])
               + W2 * (a[1] + a[5]) + W3 * (a[0] + a[6]);
#pragma unroll
            for (int k = 6; k >= 1; k--) a[k] = a[k - 1];
            a[0] = na;
            z--;
        }
    }
    s_sum[chunk][cl] = S;
    __syncthreads();

    float Xoff = 0.f;
#pragma unroll
    for (int c = 0; c < 15; c++)
        if (c < chunk) Xoff += s_sum[c][cl];

    // ---------------- Boundary state for chunk > 0 ------------------------
    float tprev = 0.f, vprev = 0.f;
    if (chunk > 0) {
        int zb = z0 + 1;   // z at zf = 8*chunk - 1; taps all in [0,127]
        vprev = W0 * sB[zb][cl]
              + W1 * (sB[zb - 1][cl] + sB[zb + 1][cl])
              + W2 * (sB[zb - 2][cl] + sB[zb + 2][cl])
              + W3 * (sB[zb - 3][cl] + sB[zb + 3][cl]);
        tprev = (Xoff * 20.f + 1.f) * __expf(-20.f * Xoff);
    }

    // ---------------- Phase 2: full evaluation ----------------------------
    float b[7];
#pragma unroll
    for (int k = 0; k < 7; k++) {
        int zi = z0 + k - 3;
        if ((unsigned)zi < 128u) {
            a[k] = sA[zi][cl];
            b[k] = sB[zi][cl];
        } else {
            a[k] = 0.f; b[k] = 0.f;
        }
    }

    float xacc = Xoff, iv = 0.f;
    int z = z0;
#pragma unroll
    for (int i = 0; i < 8; i++) {
        int pz = z - 4;
        float na = 0.f, nb = 0.f;
        if (pz >= 0) { na = sA[pz][cl]; nb = sB[pz][cl]; }

        float ds_s = W0 * a[3] + W1 * (a[2] + a[4])
                   + W2 * (a[1] + a[5]) + W3 * (a[0] + a[6]);
        float vn_s = W0 * b[3] + W1 * (b[2] + b[4])
                   + W2 * (b[1] + b[5]) + W3 * (b[0] + b[6]);

        xacc += ds_s;
        float tt = (xacc * 20.f + 1.f) * __expf(-20.f * xacc);

        if (i == 0 && chunk == 0)
            iv = (1.f - tt) * vn_s;                       // front term
        else
            iv += (tprev - tt) * (vprev + vn_s) * 0.5f;   // trapezoid
        tprev = tt; vprev = vn_s;

#pragma unroll
        for (int k = 6; k >= 1; k--) { a[k] = a[k - 1]; b[k] = b[k - 1]; }
        a[0] = na; b[0] = nb;
        z--;
    }

    s_iv[chunk][cl] = iv;
    __syncthreads();

    if (chunk == 0) {
        float tot = iv;
#pragma unroll
        for (int c = 1; c < 16; c++) tot += s_iv[c][cl];
        out[colg0 + cl] = fminf(fmaxf(tot, 0.f), 1.f);
    }
}

// ---------------------------------------------------------------------------
extern "C" void kernel_launch(void* const* d_in, const int* in_sizes, int n_in,
                              void* d_out, int out_size) {
    const float* d = (const float*)d_in[0];
    const float* v = (const float*)d_in[1];
    if (in_sizes[0] > in_sizes[1]) {   // safety: d is the smaller tensor
        const float* tmp = d; d = v; v = tmp;
    }
    float* out = (float*)d_out;

    dim3 g2(128 / TSY, NB * 128);             // (y-tile, n*z)
    fused_smooth_kernel<<<g2, 256>>>(d, v);   // g_a (d) and g_b (|curl v|)

    integrate_kernel<<<65536 / 32, 512>>>(out);
}

// round 13
// speedup vs baseline: 1.7580x; 1.0068x over previous
#include <cuda_runtime.h>
#include <math.h>

#define VOL   2097152              // 128^3
#define NB    4
#define S2D   16384                // 128*128 (z stride)

// Normalized 1-D Gaussian weights (sigma=1.6, 7 taps), sum = 1.
#define W0 0.25603832f   // center
#define W1 0.21061137f   // +-1
#define W2 0.11722290f   // +-2
#define W3 0.04414655f   // +-3

// Scratch (allocation-free contract: __device__ globals)
__device__ float g_a [(size_t)NB * VOL];   // d   smoothed in x,y
__device__ float g_b [(size_t)NB * VOL];   // |curl v| smoothed in x,y

#define TSY 32
#define LDY 38    // TSY + 6 (y halo rows)
#define NQB 34    // phase-B halo quads per row: gx in [-4, 132)
#define SIN 140   // s_in row stride (floats): 136 data + 4 pad (560B, 16B mult)

#define F4Z make_float4(0.f, 0.f, 0.f, 0.f)

// 7-tap x-conv of a 4-wide output quad from three f4 windows:
// a = values at ox-4.., b = ox.., c = ox+4..
__device__ __forceinline__ float4 xconv(float4 a, float4 b, float4 c) {
    float4 r;
    r.x = W0 * b.x + W1 * (a.w + b.y) + W2 * (a.z + b.z) + W3 * (a.y + b.w);
    r.y = W0 * b.y + W1 * (b.x + b.z) + W2 * (a.w + b.w) + W3 * (a.z + c.x);
    r.z = W0 * b.z + W1 * (b.y + b.w) + W2 * (b.x + c.x) + W3 * (a.w + c.y);
    r.w = W0 * b.w + W1 * (b.z + c.x) + W2 * (b.y + c.y) + W3 * (b.x + c.z);
    return r;
}

// y-pass: one output quad column x 4 rows from a 10-row register window.
// itm in [0,256): ox = (itm&31)*4, oy = (itm>>5)*4.
__device__ __forceinline__ void ypass_store(const float (*s_tmp)[128],
                                            float* outp, int ty0, int itm) {
    int ox = (itm & 31) * 4;
    int oy = (itm >> 5) * 4;
    float4 t[10];
#pragma unroll
    for (int r = 0; r < 10; r++)
        t[r] = *(const float4*)&s_tmp[oy + r][ox];
#pragma unroll
    for (int j = 0; j < 4; j++) {
        float4 r4;
        r4.x = W0 * t[j+3].x + W1 * (t[j+2].x + t[j+4].x)
             + W2 * (t[j+1].x + t[j+5].x) + W3 * (t[j].x + t[j+6].x);
        r4.y = W0 * t[j+3].y + W1 * (t[j+2].y + t[j+4].y)
             + W2 * (t[j+1].y + t[j+5].y) + W3 * (t[j].y + t[j+6].y);
        r4.z = W0 * t[j+3].z + W1 * (t[j+2].z + t[j+4].z)
             + W2 * (t[j+1].z + t[j+5].z) + W3 * (t[j].z + t[j+6].z);
        r4.w = W0 * t[j+3].w + W1 * (t[j+2].w + t[j+4].w)
             + W2 * (t[j+1].w + t[j+5].w) + W3 * (t[j].w + t[j+6].w);
        *(float4*)(outp + (ty0 + oy + j) * 128 + ox) = r4;
    }
}

// ---------------------------------------------------------------------------
// Fused kernel, full-width 128x32 tiles (UNCHANGED — protected at ~51us):
//   phase A: d -> x-conv DIRECTLY from global (no staging) -> s_tmp -> y-pass -> g_a
//   phase B: |curl v| halo -> s_in -> x-pass -> s_tmp -> y-pass -> g_b
// ---------------------------------------------------------------------------
__global__ __launch_bounds__(256)
void fused_smooth_kernel(const float* __restrict__ d,
                         const float* __restrict__ v) {
    int ty0 = blockIdx.x * TSY;
    int nz  = blockIdx.y;            // n*128 + z
    int n = nz >> 7, z = nz & 127;

    __shared__ __align__(16) float s_in [LDY][SIN];
    __shared__ __align__(16) float s_tmp[LDY][128];

    int tid = threadIdx.x;

    // ============ phase A : x-conv of d straight from global =============
    {
        const float* slice = d + (size_t)n * VOL + z * S2D;
        for (int i = tid; i < LDY * 32; i += 256) {
            int ly = i >> 5, qx = i & 31;
            int gy = ty0 + ly - 3, ox = qx * 4;
            float4 a = F4Z, b = F4Z, c = F4Z;
            if ((unsigned)gy < 128u) {
                const float* row = slice + gy * 128;
                if (qx >= 1)  a = *(const float4*)(row + ox - 4);
                b = *(const float4*)(row + ox);
                if (qx <= 30) c = *(const float4*)(row + ox + 4);
            }
            *(float4*)&s_tmp[ly][ox] = xconv(a, b, c);
        }
    }
    __syncthreads();

    // A y-pass (reads s_tmp only) — overlaps with phase-B halo (writes s_in)
    ypass_store(s_tmp, g_a + (size_t)n * VOL + z * S2D, ty0, tid);

    // ======================= phase B : |curl v| halo ======================
    {
        const float* pu = v + (size_t)(n * 3 + 0) * VOL + z * S2D;
        const float* pv = v + (size_t)(n * 3 + 1) * VOL + z * S2D;
        const float* pw = v + (size_t)(n * 3 + 2) * VOL + z * S2D;
        const int   dzo = (z < 127) ? S2D : -S2D;
        const float ez  = (z < 127) ? 1.f : -1.f;

        for (int i = tid; i < LDY * NQB; i += 256) {
            int ly = i / NQB, q = i - ly * NQB;
            int gy = ty0 + ly - 3, gx = q * 4 - 4;
            float4 val = F4Z;
            if ((unsigned)gy < 128u && (unsigned)gx < 128u) {
                int   o   = gy * 128 + gx;
                int   dyo = (gy < 127) ? 128 : -128;
                float ey  = (gy < 127) ? 1.f : -1.f;

                float4 uc = *(const float4*)(pu + o);
                float4 uz = *(const float4*)(pu + o + dzo);
                float4 uy = *(const float4*)(pu + o + dyo);
                float4 vc = *(const float4*)(pv + o);
                float4 vz = *(const float4*)(pv + o + dzo);
                float4 wc = *(const float4*)(pw + o);
                float4 wy = *(const float4*)(pw + o + dyo);
                float vn4 = 0.f, wn4 = 0.f;
                if (gx + 4 < 128) { vn4 = pv[o + 4]; wn4 = pw[o + 4]; }

                // z-derivatives
                float duz0 = ez * (uz.x - uc.x), duz1 = ez * (uz.y - uc.y);
                float duz2 = ez * (uz.z - uc.z), duz3 = ez * (uz.w - uc.w);
                float dvz0 = ez * (vz.x - vc.x), dvz1 = ez * (vz.y - vc.y);
                float dvz2 = ez * (vz.z - vc.z), dvz3 = ez * (vz.w - vc.w);
                // y-derivatives
                float duy0 = ey * (uy.x - uc.x), duy1 = ey * (uy.y - uc.y);
                float duy2 = ey * (uy.z - uc.z), duy3 = ey * (uy.w - uc.w);
                float dwy0 = ey * (wy.x - wc.x), dwy1 = ey * (wy.y - wc.y);
                float dwy2 = ey * (wy.z - wc.z), dwy3 = ey * (wy.w - wc.w);
                // x-derivatives (quad-internal; .w uses neighbor or clamp)
                float dvx0 = vc.y - vc.x, dvx1 = vc.z - vc.y, dvx2 = vc.w - vc.z;
                float dwx0 = wc.y - wc.x, dwx1 = wc.z - wc.y, dwx2 = wc.w - wc.z;
                float dvx3, dwx3;
                if (gx + 3 < 127) { dvx3 = vn4 - vc.w;  dwx3 = wn4 - wc.w; }
                else              { dvx3 = vc.w - vc.z; dwx3 = wc.w - wc.z; }

                float cu0 = dwy0 - dvz0, cv0 = duz0 - dwx0, cw0 = dvx0 - duy0;
                float cu1 = dwy1 - dvz1, cv1 = duz1 - dwx1, cw1 = dvx1 - duy1;
                float cu2 = dwy2 - dvz2, cv2 = duz2 - dwx2, cw2 = dvx2 - duy2;
                float cu3 = dwy3 - dvz3, cv3 = duz3 - dwx3, cw3 = dvx3 - duy3;
                val.x = sqrtf(cu0 * cu0 + cv0 * cv0 + cw0 * cw0);
                val.y = sqrtf(cu1 * cu1 + cv1 * cv1 + cw1 * cw1);
                val.z = sqrtf(cu2 * cu2 + cv2 * cv2 + cw2 * cw2);
                val.w = sqrtf(cu3 * cu3 + cv3 * cv3 + cw3 * cw3);
            }
            *(float4*)&s_in[ly][q * 4] = val;   // lx = gx + 4
        }
    }
    __syncthreads();   // orders A y-pass s_tmp reads & B halo s_in writes

    // B x-pass: s_in lx = gx+4, so output quad ox reads lx = ox, ox+4, ox+8
    for (int i = tid; i < LDY * 32; i += 256) {
        int ly = i >> 5, ox = (i & 31) * 4;
        float4 a = *(const float4*)&s_in[ly][ox];
        float4 b = *(const float4*)&s_in[ly][ox + 4];
        float4 c = *(const float4*)&s_in[ly][ox + 8];
        *(float4*)&s_tmp[ly][ox] = xconv(a, b, c);
    }
    __syncthreads();

    ypass_store(s_tmp, g_b + (size_t)n * VOL + z * S2D, ty0, tid);
}

// ---------------------------------------------------------------------------
// Integrate kernel: fused Z-smooth + flip + cumsum + transform + trapezoid
// + clip. 512 threads = 32 columns x 16 chunks of 8 zf-steps.
// Phase 1 now SAVES its 8 smoothed-ds values in registers (dss[8]); phase 2
// drops the entire A-side window (no A LDS, no A conv) and replays dss[].
// ---------------------------------------------------------------------------
__global__ __launch_bounds__(512)
void integrate_kernel(float* __restrict__ out) {
    __shared__ float sA[128][32];
    __shared__ float sB[128][32];
    __shared__ float s_sum[16][32];
    __shared__ float s_iv [16][32];

    int tid   = threadIdx.x;
    int cl    = tid & 31;                    // column within block
    int chunk = tid >> 5;                    // 0..15 (one warp per chunk)

    int colg0 = blockIdx.x * 32;
    int n   = colg0 >> 14;
    int yx0 = colg0 & 16383;                 // 16384 % 32 == 0: no n straddle

    const float* Abase = g_a + (size_t)n * VOL + yx0;
    const float* Bbase = g_b + (size_t)n * VOL + yx0;

    // ---------------- Phase 0: stage columns ------------------------------
    for (int i = tid; i < 128 * 8; i += 512) {      // 8 float4 per z-row
        int z = i >> 3, c4 = (i & 7) << 2;
        *(float4*)&sA[z][c4] = *(const float4*)(Abase + z * S2D + c4);
        *(float4*)&sB[z][c4] = *(const float4*)(Bbase + z * S2D + c4);
    }
    __syncthreads();

    const int z0 = 127 - 8 * chunk;          // first z of this chunk (walk down)

    // ---------------- Phase 1: smoothed ds values (kept in registers) -----
    float dss[8];
    float S = 0.f;
    {
        float a[7];
#pragma unroll
        for (int k = 0; k < 7; k++) {
            int zi = z0 + k - 3;
            a[k] = ((unsigned)zi < 128u) ? sA[zi][cl] : 0.f;
        }
        int z = z0;
#pragma unroll
        for (int i = 0; i < 8; i++) {
            int pz = z - 4;
            float na = (pz >= 0) ? sA[pz][cl] : 0.f;
            float ds = W0 * a[3] + W1 * (a[2] + a[4])
                     + W2 * (a[1] + a[5]) + W3 * (a[0] + a[6]);
            dss[i] = ds;
            S += ds;
#pragma unroll
            for (int k = 6; k >= 1; k--) a[k] = a[k - 1];
            a[0] = na;
            z--;
        }
    }
    s_sum[chunk][cl] = S;
    __syncthreads();

    float Xoff = 0.f;
#pragma unroll
    for (int c = 0; c < 15; c++)
        if (c < chunk) Xoff += s_sum[c][cl];

    // ---------------- Boundary state for chunk > 0 ------------------------
    float tprev = 0.f, vprev = 0.f;
    if (chunk > 0) {
        int zb = z0 + 1;   // z at zf = 8*chunk - 1; taps all in [0,127]
        vprev = W0 * sB[zb][cl]
              + W1 * (sB[zb - 1][cl] + sB[zb + 1][cl])
              + W2 * (sB[zb - 2][cl] + sB[zb + 2][cl])
              + W3 * (sB[zb - 3][cl] + sB[zb + 3][cl]);
        tprev = (Xoff * 20.f + 1.f) * __expf(-20.f * Xoff);
    }

    // ---------------- Phase 2: B-side only (A replayed from dss[]) --------
    float b[7];
#pragma unroll
    for (int k = 0; k < 7; k++) {
        int zi = z0 + k - 3;
        b[k] = ((unsigned)zi < 128u) ? sB[zi][cl] : 0.f;
    }

    float xacc = Xoff, iv = 0.f;
    int z = z0;
#pragma unroll
    for (int i = 0; i < 8; i++) {
        int pz = z - 4;
        float nb = (pz >= 0) ? sB[pz][cl] : 0.f;

        float vn_s = W0 * b[3] + W1 * (b[2] + b[4])
                   + W2 * (b[1] + b[5]) + W3 * (b[0] + b[6]);

        xacc += dss[i];
        float tt = (xacc * 20.f + 1.f) * __expf(-20.f * xacc);

        if (i == 0 && chunk == 0)
            iv = (1.f - tt) * vn_s;                       // front term
        else
            iv += (tprev - tt) * (vprev + vn_s) * 0.5f;   // trapezoid
        tprev = tt; vprev = vn_s;

#pragma unroll
        for (int k = 6; k >= 1; k--) b[k] = b[k - 1];
        b[0] = nb;
        z--;
    }

    s_iv[chunk][cl] = iv;
    __syncthreads();

    if (chunk == 0) {
        float tot = iv;
#pragma unroll
        for (int c = 1; c < 16; c++) tot += s_iv[c][cl];
        out[colg0 + cl] = fminf(fmaxf(tot, 0.f), 1.f);
    }
}

// ---------------------------------------------------------------------------
extern "C" void kernel_launch(void* const* d_in, const int* in_sizes, int n_in,
                              void* d_out, int out_size) {
    const float* d = (const float*)d_in[0];
    const float* v = (const float*)d_in[1];
    if (in_sizes[0] > in_sizes[1]) {   // safety: d is the smaller tensor
        const float* tmp = d; d = v; v = tmp;
    }
    float* out = (float*)d_out;

    dim3 g2(128 / TSY, NB * 128);             // (y-tile, n*z)
    fused_smooth_kernel<<<g2, 256>>>(d, v);   // g_a (d) and g_b (|curl v|)

    integrate_kernel<<<65536 / 32, 512>>>(out);
}